// round 3
// baseline (speedup 1.0000x reference)
#include <cuda_runtime.h>
#include <math.h>

// ---------------- problem constants ----------------
constexpr int NN  = 65536;      // nodes
constexpr int DD  = 256;        // hidden
constexpr int EE  = 524288;     // edges
constexpr int LL  = 4;          // layers
constexpr int GG  = 512;        // graphs
constexpr int NPG = 128;        // nodes per graph
constexpr int HH  = 8;          // heads
constexpr int DHH = 32;         // head dim
constexpr int WW  = 20;         // walk length (pe dim)
constexpr int AV  = 128;        // atom vocab
constexpr int BV  = 8;          // bond vocab
constexpr int FF  = 512;        // mlp hidden

// ---------------- scratch (device globals; no alloc allowed) ----------------
__device__ float g_h   [NN * DD];
__device__ float g_z   [NN * DD];
__device__ float g_t1  [NN * DD];
__device__ float g_t2  [NN * DD];
__device__ float g_hl  [NN * DD];
__device__ float g_ha  [NN * DD];
__device__ float g_qkv [NN * 3 * DD];
__device__ float g_attn[NN * DD];
__device__ float g_ff  [NN * FF];
__device__ float g_sum [DD];
__device__ float g_ss  [DD];

// ---------------- encode: h = sum_c atom_emb[c, x[n,c]] + pe @ pe_w + pe_b ----------------
__global__ void k_encode(const int* __restrict__ x, const float* __restrict__ pe,
                         const float* __restrict__ atom, const float* __restrict__ pe_w,
                         const float* __restrict__ pe_b) {
    int n = blockIdx.x;
    int d = threadIdx.x * 4;           // 64 threads, float4 over 256 dims
    __shared__ int   xs[9];
    __shared__ float ps[WW];
    if (threadIdx.x < 9) xs[threadIdx.x] = x[n * 9 + threadIdx.x];
    if (threadIdx.x >= 32 && threadIdx.x < 32 + WW) ps[threadIdx.x - 32] = pe[n * WW + (threadIdx.x - 32)];
    __syncthreads();
    float4 acc = *(const float4*)(pe_b + d);
#pragma unroll
    for (int c = 0; c < 9; c++) {
        float4 v = *(const float4*)(atom + ((long)(c * AV + xs[c]) * DD + d));
        acc.x += v.x; acc.y += v.y; acc.z += v.z; acc.w += v.w;
    }
#pragma unroll
    for (int w = 0; w < WW; w++) {
        float p = ps[w];
        float4 v = *(const float4*)(pe_w + (long)w * DD + d);
        acc.x = fmaf(p, v.x, acc.x); acc.y = fmaf(p, v.y, acc.y);
        acc.z = fmaf(p, v.z, acc.z); acc.w = fmaf(p, v.w, acc.w);
    }
    *(float4*)(g_h + (long)n * DD + d) = acc;
}

// ---------------- GINE message + scatter: z[dst] += relu(h[src] + ea) ----------------
// 4 edges per 256-thread block; 64 threads (float4) per edge.
__global__ void k_scatter(const int* __restrict__ ei, const int* __restrict__ eattr,
                          const float* __restrict__ bond) {
    int le = threadIdx.x >> 6;
    int d  = (threadIdx.x & 63) * 4;
    long e = (long)blockIdx.x * 4 + le;
    int src = ei[e];
    int dst = ei[(long)EE + e];
    int a0 = eattr[e * 3 + 0], a1 = eattr[e * 3 + 1], a2 = eattr[e * 3 + 2];
    float4 hv = *(const float4*)(g_h + (long)src * DD + d);
    float4 b0 = *(const float4*)(bond + (long)(0 * BV + a0) * DD + d);
    float4 b1 = *(const float4*)(bond + (long)(1 * BV + a1) * DD + d);
    float4 b2 = *(const float4*)(bond + (long)(2 * BV + a2) * DD + d);
    float m0 = fmaxf(hv.x + b0.x + b1.x + b2.x, 0.f);
    float m1 = fmaxf(hv.y + b0.y + b1.y + b2.y, 0.f);
    float m2 = fmaxf(hv.z + b0.z + b1.z + b2.z, 0.f);
    float m3 = fmaxf(hv.w + b0.w + b1.w + b2.w, 0.f);
    float* zp = g_z + (long)dst * DD + d;
    atomicAdd(zp + 0, m0); atomicAdd(zp + 1, m1);
    atomicAdd(zp + 2, m2); atomicAdd(zp + 3, m3);
}

// ---------------- SGEMM: C[M,Nn] = A[M,K] @ B[K,Nn] + bias (+relu) ----------------
// 128x128 block tile, 8 K-step, 256 threads, 8x8 per-thread tile.
__global__ void __launch_bounds__(256) k_sgemm(const float* __restrict__ A,
                                               const float* __restrict__ B,
                                               const float* __restrict__ bias,
                                               float* __restrict__ C,
                                               int M, int Nn, int K, int relu) {
    __shared__ float As[8][128];
    __shared__ float Bs[8][128];
    int tid = threadIdx.x;
    int m0 = blockIdx.y * 128, n0 = blockIdx.x * 128;
    int ty = tid >> 4, tx = tid & 15;

    float acc[8][8];
#pragma unroll
    for (int i = 0; i < 8; i++)
#pragma unroll
        for (int j = 0; j < 8; j++) acc[i][j] = 0.f;

    int a_m = tid >> 1, a_k = (tid & 1) * 4;
    int b_k = tid >> 5, b_n = (tid & 31) * 4;
    const float* Ap = A + (long)(m0 + a_m) * K + a_k;
    const float* Bp = B + (long)b_k * Nn + n0 + b_n;

    for (int k0 = 0; k0 < K; k0 += 8) {
        float4 va = *(const float4*)(Ap + k0);
        float4 vb = *(const float4*)(Bp + (long)k0 * Nn);
        As[a_k + 0][a_m] = va.x; As[a_k + 1][a_m] = va.y;
        As[a_k + 2][a_m] = va.z; As[a_k + 3][a_m] = va.w;
        *(float4*)(&Bs[b_k][b_n]) = vb;
        __syncthreads();
#pragma unroll
        for (int k = 0; k < 8; k++) {
            float a[8], b[8];
            *(float4*)(a)     = *(const float4*)(&As[k][ty * 8]);
            *(float4*)(a + 4) = *(const float4*)(&As[k][ty * 8 + 4]);
            *(float4*)(b)     = *(const float4*)(&Bs[k][tx * 8]);
            *(float4*)(b + 4) = *(const float4*)(&Bs[k][tx * 8 + 4]);
#pragma unroll
            for (int i = 0; i < 8; i++)
#pragma unroll
                for (int j = 0; j < 8; j++) acc[i][j] = fmaf(a[i], b[j], acc[i][j]);
        }
        __syncthreads();
    }
#pragma unroll
    for (int i = 0; i < 8; i++) {
        long row = m0 + ty * 8 + i;
#pragma unroll
        for (int j = 0; j < 8; j += 4) {
            float4 bv = *(const float4*)(bias + n0 + tx * 8 + j);
            float4 o;
            o.x = acc[i][j + 0] + bv.x; o.y = acc[i][j + 1] + bv.y;
            o.z = acc[i][j + 2] + bv.z; o.w = acc[i][j + 3] + bv.w;
            if (relu) {
                o.x = fmaxf(o.x, 0.f); o.y = fmaxf(o.y, 0.f);
                o.z = fmaxf(o.z, 0.f); o.w = fmaxf(o.w, 0.f);
            }
            *(float4*)(C + row * Nn + n0 + tx * 8 + j) = o;
        }
    }
}

// ---------------- BatchNorm stats over node axis ----------------
__global__ void k_zero_stats() {
    int t = threadIdx.x;
    if (t < DD) { g_sum[t] = 0.f; g_ss[t] = 0.f; }
}

__global__ void k_colstats(const float* __restrict__ A, const float* __restrict__ B) {
    int t = threadIdx.x;                 // column
    long r0 = (long)blockIdx.x * 256;
    float s = 0.f, ss = 0.f;
    for (int r = 0; r < 256; r++) {
        float v = A[(r0 + r) * DD + t];
        if (B) v += B[(r0 + r) * DD + t];
        s += v; ss += v * v;
    }
    atomicAdd(&g_sum[t], s);
    atomicAdd(&g_ss[t], ss);
}

__global__ void k_bn(const float* __restrict__ A, const float* __restrict__ B,
                     const float* __restrict__ gma, const float* __restrict__ bta,
                     float* __restrict__ O, int relu) {
    long i = (long)blockIdx.x * blockDim.x + threadIdx.x;
    int d = (int)(i & (DD - 1));
    float mu  = g_sum[d] * (1.f / NN);
    float var = g_ss[d] * (1.f / NN) - mu * mu;
    float v = A[i];
    if (B) v += B[i];
    v = (v - mu) * rsqrtf(var + 1e-5f) * gma[d] + bta[d];
    if (relu) v = fmaxf(v, 0.f);
    O[i] = v;
}

__global__ void k_addv(const float* __restrict__ A, const float* __restrict__ B,
                       float* __restrict__ O) {
    long i = (long)blockIdx.x * blockDim.x + threadIdx.x;
    O[i] = A[i] + B[i];
}

// ---------------- per-(graph, head) dense attention ----------------
// smem: K[128*33], V[128*33], S[128*129]  (padded, conflict-free)
constexpr int ATTN_SMEM = (2 * NPG * 33 + NPG * 129) * 4;
__global__ void k_attention() {
    extern __shared__ float sm[];
    float* Ks = sm;
    float* Vs = Ks + NPG * 33;
    float* Ss = Vs + NPG * 33;
    int head = blockIdx.x, g = blockIdx.y;
    int i = threadIdx.x;                              // query row 0..127
    const float* base = g_qkv + (long)(g * NPG + i) * (3 * DD);

    float q[DHH];
#pragma unroll
    for (int k = 0; k < DHH; k++) {
        q[k] = base[head * DHH + k];
        Ks[i * 33 + k] = base[DD + head * DHH + k];
        Vs[i * 33 + k] = base[2 * DD + head * DHH + k];
    }
    __syncthreads();

    const float scale = 0.17677669529663688f;         // 1/sqrt(32)
    float mx = -1e30f;
#pragma unroll 4
    for (int j = 0; j < NPG; j++) {
        float s = 0.f;
#pragma unroll
        for (int k = 0; k < DHH; k++) s = fmaf(q[k], Ks[j * 33 + k], s);
        s *= scale;
        Ss[i * 129 + j] = s;
        mx = fmaxf(mx, s);
    }
    float denom = 0.f;
#pragma unroll 4
    for (int j = 0; j < NPG; j++) {
        float p = __expf(Ss[i * 129 + j] - mx);
        Ss[i * 129 + j] = p;
        denom += p;
    }
    float inv = 1.f / denom;
    float o[DHH];
#pragma unroll
    for (int k = 0; k < DHH; k++) o[k] = 0.f;
#pragma unroll 4
    for (int j = 0; j < NPG; j++) {
        float p = Ss[i * 129 + j];
#pragma unroll
        for (int k = 0; k < DHH; k++) o[k] = fmaf(p, Vs[j * 33 + k], o[k]);
    }
    float* op = g_attn + (long)(g * NPG + i) * DD + head * DHH;
#pragma unroll
    for (int k = 0; k < DHH; k++) op[k] = o[k] * inv;
}

// ---------------- global add pool (contiguous 128-node graphs) ----------------
__global__ void k_pool(float* __restrict__ out) {
    int g = blockIdx.x, d = threadIdx.x;
    float s = 0.f;
    for (int i = 0; i < NPG; i++) s += g_h[(long)(g * NPG + i) * DD + d];
    out[g * DD + d] = s;
}

// ---------------- host orchestration ----------------
static void sgemm_launch(const float* A, const float* B, const float* bias, float* C,
                         int M, int Nn, int K, int relu) {
    dim3 grid(Nn / 128, M / 128);
    k_sgemm<<<grid, 256>>>(A, B, bias, C, M, Nn, K, relu);
}

extern "C" void kernel_launch(void* const* d_in, const int* in_sizes, int n_in,
                              void* d_out, int out_size) {
    const int*   x     = (const int*)d_in[0];
    const int*   ei    = (const int*)d_in[1];
    const int*   eattr = (const int*)d_in[2];
    /* d_in[3] = batch (contiguous by construction, unused) */
    const float* pe    = (const float*)d_in[4];
    const float* atom  = (const float*)d_in[5];
    const float* bond  = (const float*)d_in[6];
    const float* pe_w  = (const float*)d_in[7];
    const float* pe_b  = (const float*)d_in[8];
    const float* gw1   = (const float*)d_in[9];
    const float* gb1   = (const float*)d_in[10];
    const float* gg1   = (const float*)d_in[11];
    const float* gbe1  = (const float*)d_in[12];
    const float* gw2   = (const float*)d_in[13];
    const float* gb2   = (const float*)d_in[14];
    const float* wqkv  = (const float*)d_in[15];
    const float* bqkv  = (const float*)d_in[16];
    const float* wo    = (const float*)d_in[17];
    const float* bo    = (const float*)d_in[18];
    const float* n1g   = (const float*)d_in[19];
    const float* n1b   = (const float*)d_in[20];
    const float* n2g   = (const float*)d_in[21];
    const float* n2b   = (const float*)d_in[22];
    const float* n3g   = (const float*)d_in[23];
    const float* n3b   = (const float*)d_in[24];
    const float* mw1   = (const float*)d_in[25];
    const float* mb1   = (const float*)d_in[26];
    const float* mw2   = (const float*)d_in[27];
    const float* mb2   = (const float*)d_in[28];

    float *h, *z, *t1, *t2, *hl, *ha, *qkv, *attn, *ff;
    cudaGetSymbolAddress((void**)&h,    g_h);
    cudaGetSymbolAddress((void**)&z,    g_z);
    cudaGetSymbolAddress((void**)&t1,   g_t1);
    cudaGetSymbolAddress((void**)&t2,   g_t2);
    cudaGetSymbolAddress((void**)&hl,   g_hl);
    cudaGetSymbolAddress((void**)&ha,   g_ha);
    cudaGetSymbolAddress((void**)&qkv,  g_qkv);
    cudaGetSymbolAddress((void**)&attn, g_attn);
    cudaGetSymbolAddress((void**)&ff,   g_ff);

    cudaFuncSetAttribute(k_attention, cudaFuncAttributeMaxDynamicSharedMemorySize, ATTN_SMEM);

    const long ND = (long)NN * DD;
    const int EW_BLOCKS = (int)(ND / 256);

    k_encode<<<NN, 64>>>(x, pe, atom, pe_w, pe_b);

    for (int l = 0; l < LL; l++) {
        // --- GINEConv ---
        cudaMemcpyAsync(z, h, ND * sizeof(float), cudaMemcpyDeviceToDevice);
        k_scatter<<<EE / 4, 256>>>(ei, eattr, bond);                      // z = h + agg
        sgemm_launch(z, gw1 + (long)l * DD * DD, gb1 + l * DD, t1, NN, DD, DD, 0);
        k_zero_stats<<<1, 256>>>();
        k_colstats<<<256, 256>>>(t1, nullptr);
        k_bn<<<EW_BLOCKS, 256>>>(t1, nullptr, gg1 + l * DD, gbe1 + l * DD, t2, 1);
        sgemm_launch(t2, gw2 + (long)l * DD * DD, gb2 + l * DD, t1, NN, DD, DD, 1);
        k_zero_stats<<<1, 256>>>();
        k_colstats<<<256, 256>>>(t1, h);
        k_bn<<<EW_BLOCKS, 256>>>(t1, h, n1g + l * DD, n1b + l * DD, hl, 0);  // h_local

        // --- attention branch (on layer-input h) ---
        sgemm_launch(h, wqkv + (long)l * DD * 3 * DD, bqkv + l * 3 * DD, qkv, NN, 3 * DD, DD, 0);
        k_attention<<<dim3(HH, GG), NPG, ATTN_SMEM>>>();
        sgemm_launch(attn, wo + (long)l * DD * DD, bo + l * DD, t1, NN, DD, DD, 0);
        k_zero_stats<<<1, 256>>>();
        k_colstats<<<256, 256>>>(t1, h);
        k_bn<<<EW_BLOCKS, 256>>>(t1, h, n2g + l * DD, n2b + l * DD, ha, 0);  // h_attn

        // --- combine + MLP + norm3 ---
        k_addv<<<EW_BLOCKS, 256>>>(hl, ha, t2);
        sgemm_launch(t2, mw1 + (long)l * DD * FF, mb1 + l * FF, ff, NN, FF, DD, 1);
        sgemm_launch(ff, mw2 + (long)l * FF * DD, mb2 + l * DD, t1, NN, DD, FF, 0);
        k_zero_stats<<<1, 256>>>();
        k_colstats<<<256, 256>>>(t1, nullptr);
        k_bn<<<EW_BLOCKS, 256>>>(t1, nullptr, n3g + l * DD, n3b + l * DD, h, 0);
    }

    k_pool<<<GG, DD>>>((float*)d_out);
}

// round 10
// speedup vs baseline: 1.4603x; 1.4603x over previous
#include <cuda_runtime.h>
#include <cuda_bf16.h>
#include <math.h>
#include <stdint.h>

// ---------------- problem constants ----------------
constexpr int NN  = 65536;      // nodes
constexpr int DD  = 256;        // hidden
constexpr int EE  = 524288;     // edges
constexpr int LL  = 4;          // layers
constexpr int GG  = 512;        // graphs
constexpr int NPG = 128;        // nodes per graph
constexpr int HH  = 8;          // heads
constexpr int DHH = 32;         // head dim
constexpr int WW  = 20;         // walk length (pe dim)
constexpr int AV  = 128;        // atom vocab
constexpr int BV  = 8;          // bond vocab
constexpr int FF  = 512;        // mlp hidden

// ---------------- scratch (device globals; no alloc allowed) ----------------
__device__ float g_h   [NN * DD];
__device__ float g_z   [NN * DD];
__device__ float g_t1  [NN * DD];
__device__ float g_t2  [NN * DD];
__device__ float g_hl  [NN * DD];
__device__ float g_ha  [NN * DD];
__device__ float g_qkv [NN * 3 * DD];
__device__ float g_attn[NN * DD];
__device__ float g_ff  [NN * FF];
__device__ float g_sum [DD];
__device__ float g_ss  [DD];

// transposed bf16 hi/lo weights: per layer 655360 elems
// offsets: w1=0, w2=65536, qkv=131072, wo=327680, mlp1=393216, mlp2=524288
constexpr long WL_STRIDE = 655360;
__device__ unsigned short g_wh[LL * WL_STRIDE];
__device__ unsigned short g_wl[LL * WL_STRIDE];

// =====================================================================
// helpers
// =====================================================================
__device__ __forceinline__ uint32_t smem_u32(const void* p) {
    uint32_t a;
    asm("{ .reg .u64 t; cvta.to.shared.u64 t, %1; cvt.u32.u64 %0, t; }" : "=r"(a) : "l"(p));
    return a;
}

#define STS128(r0, r1, r2, r3, smem_addr) \
    asm volatile("st.shared.v4.b32 [%0], {%1, %2, %3, %4};" \
        :: "r"(smem_addr), "r"(r0), "r"(r1), "r"(r2), "r"(r3) : "memory")

__device__ __forceinline__ void ldsm_x4(uint32_t* r, uint32_t addr) {
    asm volatile("ldmatrix.sync.aligned.m8n8.x4.shared.b16 {%0,%1,%2,%3}, [%4];"
        : "=r"(r[0]), "=r"(r[1]), "=r"(r[2]), "=r"(r[3]) : "r"(addr));
}
__device__ __forceinline__ void ldsm_x2(uint32_t* r, uint32_t addr) {
    asm volatile("ldmatrix.sync.aligned.m8n8.x2.shared.b16 {%0,%1}, [%2];"
        : "=r"(r[0]), "=r"(r[1]) : "r"(addr));
}
__device__ __forceinline__ void mma16816(float* c, const uint32_t* a, const uint32_t* b) {
    asm volatile(
        "mma.sync.aligned.m16n8k16.row.col.f32.bf16.bf16.f32 "
        "{%0,%1,%2,%3}, {%4,%5,%6,%7}, {%8,%9}, {%0,%1,%2,%3};"
        : "+f"(c[0]), "+f"(c[1]), "+f"(c[2]), "+f"(c[3])
        : "r"(a[0]), "r"(a[1]), "r"(a[2]), "r"(a[3]), "r"(b[0]), "r"(b[1]));
}

// =====================================================================
// weight prep: W[K,N] fp32 -> Wt[N,K] bf16 hi/lo
// =====================================================================
__global__ void k_wprep(const float* __restrict__ W, unsigned short* __restrict__ Wh,
                        unsigned short* __restrict__ Wl, int K, int N) {
    int i = blockIdx.x * 256 + threadIdx.x;      // i = k*N + n
    if (i >= K * N) return;
    int k = i / N, n = i % N;
    float v = W[i];
    __nv_bfloat16 h = __float2bfloat16_rn(v);
    float lo = v - __bfloat162float(h);
    __nv_bfloat16 l = __float2bfloat16_rn(lo);
    Wh[(long)n * K + k] = __bfloat16_as_ushort(h);
    Wl[(long)n * K + k] = __bfloat16_as_ushort(l);
}

// =====================================================================
// mma.sync GEMM: C[M,Nn] = (A1 (+A2)) [M,K] @ B[K,Nn] + bias (+relu)
// bf16x3 split (hi*hi + hi*lo + lo*hi), fp32 accumulate in registers.
// CTA tile 128x128, warp tile 32x64, K-chunk 64, 256 threads, occ 2.
// smem rows padded to 144B (72 bf16) -> conflict-free ldmatrix.
// =====================================================================
constexpr int ABSTRIDE = 144;                 // bytes per smem row
constexpr int SA_H = 0;
constexpr int SA_L = 128 * ABSTRIDE;          // 18432
constexpr int SB_H = 2 * 128 * ABSTRIDE;      // 36864
constexpr int SB_L = 3 * 128 * ABSTRIDE;      // 55296
constexpr int SM_TOT = 4 * 128 * ABSTRIDE;    // 73728 bytes

__device__ __forceinline__ void cvt8(float4 v0, float4 v1, uint4& hi, uint4& lo) {
    float f[8] = {v0.x, v0.y, v0.z, v0.w, v1.x, v1.y, v1.z, v1.w};
    uint32_t h[4], l[4];
#pragma unroll
    for (int i = 0; i < 4; i++) {
        __nv_bfloat16 b0 = __float2bfloat16_rn(f[2 * i]);
        __nv_bfloat16 b1 = __float2bfloat16_rn(f[2 * i + 1]);
        float r0 = f[2 * i]     - __bfloat162float(b0);
        float r1 = f[2 * i + 1] - __bfloat162float(b1);
        __nv_bfloat16 c0 = __float2bfloat16_rn(r0);
        __nv_bfloat16 c1 = __float2bfloat16_rn(r1);
        h[i] = ((uint32_t)__bfloat16_as_ushort(b1) << 16) | __bfloat16_as_ushort(b0);
        l[i] = ((uint32_t)__bfloat16_as_ushort(c1) << 16) | __bfloat16_as_ushort(c0);
    }
    hi = make_uint4(h[0], h[1], h[2], h[3]);
    lo = make_uint4(l[0], l[1], l[2], l[3]);
}

__global__ void __launch_bounds__(256, 2) k_tgemm(
    const float* __restrict__ A, const float* __restrict__ A2,
    const unsigned short* __restrict__ Bh, const unsigned short* __restrict__ Bl,
    const float* __restrict__ bias, float* __restrict__ C,
    int Nn, int K, int relu)
{
    extern __shared__ char smbuf[];
    uint32_t sb = smem_u32(smbuf);
    int tid = threadIdx.x, wid = tid >> 5, lane = tid & 31;
    int m0 = blockIdx.y * 128;
    int n0 = blockIdx.x * 128;
    const int wm = (wid & 3) * 32;       // warp M offset (4 warps over 128)
    const int wn = (wid >> 2) * 64;      // warp N offset (2 warps over 128)

    float acc[2][8][4];
#pragma unroll
    for (int i = 0; i < 2; i++)
#pragma unroll
        for (int j = 0; j < 8; j++)
#pragma unroll
            for (int q = 0; q < 4; q++) acc[i][j][q] = 0.f;

    // loader mapping: 2 threads per row, each handles 32 k-elems
    const int lr = tid >> 1;
    const int lh = (tid & 1) * 32;

    // ldmatrix per-lane patterns
    const int a_row = lane & 15;
    const int a_cb  = (lane >> 4) * 16;
    const int b_row = lane & 7;
    const int b_cb  = ((lane >> 3) & 1) * 16;

    for (int kc = 0; kc < K; kc += 64) {
        __syncthreads();     // previous chunk fully consumed
        // ---- A: load fp32 (+A2), split to bf16 hi/lo, store ----
        {
            const float4* a4 = reinterpret_cast<const float4*>(A + (long)(m0 + lr) * K + kc + lh);
            float4 av[8];
#pragma unroll
            for (int g = 0; g < 8; g++) av[g] = a4[g];
            if (A2) {
                const float4* a24 = reinterpret_cast<const float4*>(A2 + (long)(m0 + lr) * K + kc + lh);
#pragma unroll
                for (int g = 0; g < 8; g++) {
                    float4 w = a24[g];
                    av[g].x += w.x; av[g].y += w.y; av[g].z += w.z; av[g].w += w.w;
                }
            }
#pragma unroll
            for (int g = 0; g < 4; g++) {
                uint4 hi, lo;
                cvt8(av[2 * g], av[2 * g + 1], hi, lo);
                uint32_t off = (uint32_t)(lr * ABSTRIDE + lh * 2 + g * 16);
                STS128(hi.x, hi.y, hi.z, hi.w, sb + SA_H + off);
                STS128(lo.x, lo.y, lo.z, lo.w, sb + SA_L + off);
            }
        }
        // ---- B: copy bf16 hi/lo [N,K] slices ----
        {
            const uint4* bh4 = reinterpret_cast<const uint4*>(Bh + (long)(n0 + lr) * K + kc + lh);
            const uint4* bl4 = reinterpret_cast<const uint4*>(Bl + (long)(n0 + lr) * K + kc + lh);
#pragma unroll
            for (int j = 0; j < 4; j++) {
                uint32_t off = (uint32_t)(lr * ABSTRIDE + lh * 2 + j * 16);
                uint4 v = bh4[j];
                STS128(v.x, v.y, v.z, v.w, sb + SB_H + off);
                uint4 u = bl4[j];
                STS128(u.x, u.y, u.z, u.w, sb + SB_L + off);
            }
        }
        __syncthreads();
        // ---- MMA: 4 k-steps x (2 mf x 8 nf) x 3 products ----
#pragma unroll
        for (int ks = 0; ks < 4; ks++) {
            uint32_t ah[2][4], al[2][4];
#pragma unroll
            for (int mf = 0; mf < 2; mf++) {
                uint32_t aaddr = sb + SA_H +
                    (uint32_t)((wm + mf * 16 + a_row) * ABSTRIDE + ks * 32 + a_cb);
                ldsm_x4(ah[mf], aaddr);
                ldsm_x4(al[mf], aaddr + (SA_L - SA_H));
            }
#pragma unroll
            for (int nf = 0; nf < 8; nf++) {
                uint32_t baddr = sb + SB_H +
                    (uint32_t)((wn + nf * 8 + b_row) * ABSTRIDE + ks * 32 + b_cb);
                uint32_t bh2[2], bl2[2];
                ldsm_x2(bh2, baddr);
                ldsm_x2(bl2, baddr + (SB_L - SB_H));
#pragma unroll
                for (int mf = 0; mf < 2; mf++) {
                    mma16816(acc[mf][nf], ah[mf], bh2);
                    mma16816(acc[mf][nf], ah[mf], bl2);
                    mma16816(acc[mf][nf], al[mf], bh2);
                }
            }
        }
    }

    // ---- epilogue: bias (+relu), direct fp32 stores ----
#pragma unroll
    for (int mf = 0; mf < 2; mf++) {
        int row0 = m0 + wm + mf * 16 + (lane >> 2);
#pragma unroll
        for (int nf = 0; nf < 8; nf++) {
            int col = n0 + wn + nf * 8 + (lane & 3) * 2;
            float2 bv = *(const float2*)(bias + col);
            float c0 = acc[mf][nf][0] + bv.x;
            float c1 = acc[mf][nf][1] + bv.y;
            float c2 = acc[mf][nf][2] + bv.x;
            float c3 = acc[mf][nf][3] + bv.y;
            if (relu) {
                c0 = fmaxf(c0, 0.f); c1 = fmaxf(c1, 0.f);
                c2 = fmaxf(c2, 0.f); c3 = fmaxf(c3, 0.f);
            }
            float2 o0 = make_float2(c0, c1);
            float2 o1 = make_float2(c2, c3);
            *(float2*)(C + (long)row0 * Nn + col) = o0;
            *(float2*)(C + (long)(row0 + 8) * Nn + col) = o1;
        }
    }
}

// =====================================================================
// non-GEMM kernels (unchanged from passing R3 kernel)
// =====================================================================
__global__ void k_encode(const int* __restrict__ x, const float* __restrict__ pe,
                         const float* __restrict__ atom, const float* __restrict__ pe_w,
                         const float* __restrict__ pe_b) {
    int n = blockIdx.x;
    int d = threadIdx.x * 4;
    __shared__ int   xs[9];
    __shared__ float ps[WW];
    if (threadIdx.x < 9) xs[threadIdx.x] = x[n * 9 + threadIdx.x];
    if (threadIdx.x >= 32 && threadIdx.x < 32 + WW) ps[threadIdx.x - 32] = pe[n * WW + (threadIdx.x - 32)];
    __syncthreads();
    float4 acc = *(const float4*)(pe_b + d);
#pragma unroll
    for (int c = 0; c < 9; c++) {
        float4 v = *(const float4*)(atom + ((long)(c * AV + xs[c]) * DD + d));
        acc.x += v.x; acc.y += v.y; acc.z += v.z; acc.w += v.w;
    }
#pragma unroll
    for (int w = 0; w < WW; w++) {
        float p = ps[w];
        float4 v = *(const float4*)(pe_w + (long)w * DD + d);
        acc.x = fmaf(p, v.x, acc.x); acc.y = fmaf(p, v.y, acc.y);
        acc.z = fmaf(p, v.z, acc.z); acc.w = fmaf(p, v.w, acc.w);
    }
    *(float4*)(g_h + (long)n * DD + d) = acc;
}

__global__ void k_scatter(const int* __restrict__ ei, const int* __restrict__ eattr,
                          const float* __restrict__ bond) {
    int le = threadIdx.x >> 6;
    int d  = (threadIdx.x & 63) * 4;
    long e = (long)blockIdx.x * 4 + le;
    int src = ei[e];
    int dst = ei[(long)EE + e];
    int a0 = eattr[e * 3 + 0], a1 = eattr[e * 3 + 1], a2 = eattr[e * 3 + 2];
    float4 hv = *(const float4*)(g_h + (long)src * DD + d);
    float4 b0 = *(const float4*)(bond + (long)(0 * BV + a0) * DD + d);
    float4 b1 = *(const float4*)(bond + (long)(1 * BV + a1) * DD + d);
    float4 b2 = *(const float4*)(bond + (long)(2 * BV + a2) * DD + d);
    float m0 = fmaxf(hv.x + b0.x + b1.x + b2.x, 0.f);
    float m1 = fmaxf(hv.y + b0.y + b1.y + b2.y, 0.f);
    float m2 = fmaxf(hv.z + b0.z + b1.z + b2.z, 0.f);
    float m3 = fmaxf(hv.w + b0.w + b1.w + b2.w, 0.f);
    float* zp = g_z + (long)dst * DD + d;
    atomicAdd(zp + 0, m0); atomicAdd(zp + 1, m1);
    atomicAdd(zp + 2, m2); atomicAdd(zp + 3, m3);
}

__global__ void k_zero_stats() {
    int t = threadIdx.x;
    if (t < DD) { g_sum[t] = 0.f; g_ss[t] = 0.f; }
}

__global__ void k_colstats(const float* __restrict__ A, const float* __restrict__ B) {
    int t = threadIdx.x;
    long r0 = (long)blockIdx.x * 256;
    float s = 0.f, ss = 0.f;
    for (int r = 0; r < 256; r++) {
        float v = A[(r0 + r) * DD + t];
        if (B) v += B[(r0 + r) * DD + t];
        s += v; ss += v * v;
    }
    atomicAdd(&g_sum[t], s);
    atomicAdd(&g_ss[t], ss);
}

__global__ void k_bn(const float* __restrict__ A, const float* __restrict__ B,
                     const float* __restrict__ gma, const float* __restrict__ bta,
                     float* __restrict__ O, int relu) {
    long i = (long)blockIdx.x * blockDim.x + threadIdx.x;
    int d = (int)(i & (DD - 1));
    float mu  = g_sum[d] * (1.f / NN);
    float var = g_ss[d] * (1.f / NN) - mu * mu;
    float v = A[i];
    if (B) v += B[i];
    v = (v - mu) * rsqrtf(var + 1e-5f) * gma[d] + bta[d];
    if (relu) v = fmaxf(v, 0.f);
    O[i] = v;
}

constexpr int ATTN_SMEM = (2 * NPG * 33 + NPG * 129) * 4;
__global__ void k_attention() {
    extern __shared__ float sm[];
    float* Ks = sm;
    float* Vs = Ks + NPG * 33;
    float* Ss = Vs + NPG * 33;
    int head = blockIdx.x, g = blockIdx.y;
    int i = threadIdx.x;
    const float* base = g_qkv + (long)(g * NPG + i) * (3 * DD);

    float q[DHH];
#pragma unroll
    for (int k = 0; k < DHH; k++) {
        q[k] = base[head * DHH + k];
        Ks[i * 33 + k] = base[DD + head * DHH + k];
        Vs[i * 33 + k] = base[2 * DD + head * DHH + k];
    }
    __syncthreads();

    const float scale = 0.17677669529663688f;
    float mx = -1e30f;
#pragma unroll 4
    for (int j = 0; j < NPG; j++) {
        float s = 0.f;
#pragma unroll
        for (int k = 0; k < DHH; k++) s = fmaf(q[k], Ks[j * 33 + k], s);
        s *= scale;
        Ss[i * 129 + j] = s;
        mx = fmaxf(mx, s);
    }
    float denom = 0.f;
#pragma unroll 4
    for (int j = 0; j < NPG; j++) {
        float p = __expf(Ss[i * 129 + j] - mx);
        Ss[i * 129 + j] = p;
        denom += p;
    }
    float inv = 1.f / denom;
    float o[DHH];
#pragma unroll
    for (int k = 0; k < DHH; k++) o[k] = 0.f;
#pragma unroll 4
    for (int j = 0; j < NPG; j++) {
        float p = Ss[i * 129 + j];
#pragma unroll
        for (int k = 0; k < DHH; k++) o[k] = fmaf(p, Vs[j * 33 + k], o[k]);
    }
    float* op = g_attn + (long)(g * NPG + i) * DD + head * DHH;
#pragma unroll
    for (int k = 0; k < DHH; k++) op[k] = o[k] * inv;
}

__global__ void k_pool(float* __restrict__ out) {
    int g = blockIdx.x, d = threadIdx.x;
    float s = 0.f;
    for (int i = 0; i < NPG; i++) s += g_h[(long)(g * NPG + i) * DD + d];
    out[g * DD + d] = s;
}

// =====================================================================
// host orchestration
// =====================================================================
static void tgemm(const float* A, const float* A2,
                  const unsigned short* Bh, const unsigned short* Bl,
                  const float* bias, float* C, int Nn, int K, int relu) {
    dim3 grid(Nn / 128, NN / 128);
    k_tgemm<<<grid, 256, SM_TOT>>>(A, A2, Bh, Bl, bias, C, Nn, K, relu);
}

extern "C" void kernel_launch(void* const* d_in, const int* in_sizes, int n_in,
                              void* d_out, int out_size) {
    const int*   x     = (const int*)d_in[0];
    const int*   ei    = (const int*)d_in[1];
    const int*   eattr = (const int*)d_in[2];
    const float* pe    = (const float*)d_in[4];
    const float* atom  = (const float*)d_in[5];
    const float* bond  = (const float*)d_in[6];
    const float* pe_w  = (const float*)d_in[7];
    const float* pe_b  = (const float*)d_in[8];
    const float* gw1   = (const float*)d_in[9];
    const float* gb1   = (const float*)d_in[10];
    const float* gg1   = (const float*)d_in[11];
    const float* gbe1  = (const float*)d_in[12];
    const float* gw2   = (const float*)d_in[13];
    const float* gb2   = (const float*)d_in[14];
    const float* wqkv  = (const float*)d_in[15];
    const float* bqkv  = (const float*)d_in[16];
    const float* wo    = (const float*)d_in[17];
    const float* bo    = (const float*)d_in[18];
    const float* n1g   = (const float*)d_in[19];
    const float* n1b   = (const float*)d_in[20];
    const float* n2g   = (const float*)d_in[21];
    const float* n2b   = (const float*)d_in[22];
    const float* n3g   = (const float*)d_in[23];
    const float* n3b   = (const float*)d_in[24];
    const float* mw1   = (const float*)d_in[25];
    const float* mb1   = (const float*)d_in[26];
    const float* mw2   = (const float*)d_in[27];
    const float* mb2   = (const float*)d_in[28];

    float *h, *z, *t1, *t2, *hl, *ha, *qkv, *attn, *ff;
    unsigned short *wh, *wl;
    cudaGetSymbolAddress((void**)&h,    g_h);
    cudaGetSymbolAddress((void**)&z,    g_z);
    cudaGetSymbolAddress((void**)&t1,   g_t1);
    cudaGetSymbolAddress((void**)&t2,   g_t2);
    cudaGetSymbolAddress((void**)&hl,   g_hl);
    cudaGetSymbolAddress((void**)&ha,   g_ha);
    cudaGetSymbolAddress((void**)&qkv,  g_qkv);
    cudaGetSymbolAddress((void**)&attn, g_attn);
    cudaGetSymbolAddress((void**)&ff,   g_ff);
    cudaGetSymbolAddress((void**)&wh,   g_wh);
    cudaGetSymbolAddress((void**)&wl,   g_wl);

    cudaFuncSetAttribute(k_attention, cudaFuncAttributeMaxDynamicSharedMemorySize, ATTN_SMEM);
    cudaFuncSetAttribute(k_tgemm,     cudaFuncAttributeMaxDynamicSharedMemorySize, SM_TOT);

    const long ND = (long)NN * DD;
    const int EW_BLOCKS = (int)(ND / 256);

    // ---- weight split/transpose prep (bf16 hi/lo, [N,K]) ----
    for (int l = 0; l < LL; l++) {
        long off = (long)l * WL_STRIDE;
        k_wprep<<<(256 * 256 + 255) / 256, 256>>>(gw1 + (long)l * 65536,  wh + off + 0,      wl + off + 0,      256, 256);
        k_wprep<<<(256 * 256 + 255) / 256, 256>>>(gw2 + (long)l * 65536,  wh + off + 65536,  wl + off + 65536,  256, 256);
        k_wprep<<<(256 * 768 + 255) / 256, 256>>>(wqkv + (long)l * 196608, wh + off + 131072, wl + off + 131072, 256, 768);
        k_wprep<<<(256 * 256 + 255) / 256, 256>>>(wo  + (long)l * 65536,  wh + off + 327680, wl + off + 327680, 256, 256);
        k_wprep<<<(256 * 512 + 255) / 256, 256>>>(mw1 + (long)l * 131072, wh + off + 393216, wl + off + 393216, 256, 512);
        k_wprep<<<(512 * 256 + 255) / 256, 256>>>(mw2 + (long)l * 131072, wh + off + 524288, wl + off + 524288, 512, 256);
    }

    k_encode<<<NN, 64>>>(x, pe, atom, pe_w, pe_b);

    for (int l = 0; l < LL; l++) {
        long off = (long)l * WL_STRIDE;
        // --- GINEConv ---
        cudaMemcpyAsync(z, h, ND * sizeof(float), cudaMemcpyDeviceToDevice);
        k_scatter<<<EE / 4, 256>>>(ei, eattr, bond);
        tgemm(z, nullptr, wh + off + 0, wl + off + 0, gb1 + l * DD, t1, DD, DD, 0);
        k_zero_stats<<<1, 256>>>();
        k_colstats<<<256, 256>>>(t1, nullptr);
        k_bn<<<EW_BLOCKS, 256>>>(t1, nullptr, gg1 + l * DD, gbe1 + l * DD, t2, 1);
        tgemm(t2, nullptr, wh + off + 65536, wl + off + 65536, gb2 + l * DD, t1, DD, DD, 1);
        k_zero_stats<<<1, 256>>>();
        k_colstats<<<256, 256>>>(t1, h);
        k_bn<<<EW_BLOCKS, 256>>>(t1, h, n1g + l * DD, n1b + l * DD, hl, 0);  // h_local

        // --- attention branch ---
        tgemm(h, nullptr, wh + off + 131072, wl + off + 131072, bqkv + l * 3 * DD, qkv, 3 * DD, DD, 0);
        k_attention<<<dim3(HH, GG), NPG, ATTN_SMEM>>>();
        tgemm(attn, nullptr, wh + off + 327680, wl + off + 327680, bo + l * DD, t1, DD, DD, 0);
        k_zero_stats<<<1, 256>>>();
        k_colstats<<<256, 256>>>(t1, h);
        k_bn<<<EW_BLOCKS, 256>>>(t1, h, n2g + l * DD, n2b + l * DD, ha, 0);  // h_attn

        // --- combine + MLP + norm3 (addv fused into GEMM A-load) ---
        tgemm(hl, ha, wh + off + 393216, wl + off + 393216, mb1 + l * FF, ff, FF, DD, 1);
        tgemm(ff, nullptr, wh + off + 524288, wl + off + 524288, mb2 + l * DD, t1, DD, FF, 0);
        k_zero_stats<<<1, 256>>>();
        k_colstats<<<256, 256>>>(t1, nullptr);
        k_bn<<<EW_BLOCKS, 256>>>(t1, nullptr, n3g + l * DD, n3b + l * DD, h, 0);
    }

    k_pool<<<GG, DD>>>((float*)d_out);
}